// round 14
// baseline (speedup 1.0000x reference)
#include <cuda_runtime.h>
#include <cuda_bf16.h>
#include <math_constants.h>
#include <mma.h>

using namespace nvcuda;

#define BB 2
#define NN 32768
#define NQ (BB * NN)
#define MM 4096
#define MQ 512           // pairs per candidate quarter
#define NSPLIT 4
#define CC 128
#define OUTC 128
#define INC 131
#define MTILE 64

#define WSTR 148         // bf16 row stride: 74 words, gcd(74,32)=2 -> conflict-free frags
#define CSTR 132

typedef unsigned long long ull;
typedef unsigned int uint;

// ---------------------------------------------------------------------------
// Scratch (__device__ globals)
// ---------------------------------------------------------------------------
__device__ __align__(16) __nv_bfloat16 g_w1h[128 * WSTR];
__device__ __align__(16) __nv_bfloat16 g_w1l[128 * WSTR];
__device__ __align__(16) __nv_bfloat16 g_w2h[128 * WSTR];
__device__ __align__(16) __nv_bfloat16 g_w2l[128 * WSTR];
__device__ int g_idx[NQ * 3];
__device__ float g_pv[NSPLIT * NQ * 3];
__device__ int   g_pi[NSPLIT * NQ * 3];

// ---------------------------------------------------------------------------
// helpers
// ---------------------------------------------------------------------------
__device__ __forceinline__ ull fma2(ull a, ull b, ull c) {
    ull d;
    asm("fma.rn.f32x2 %0, %1, %2, %3;" : "=l"(d) : "l"(a), "l"(b), "l"(c));
    return d;
}
__device__ __forceinline__ ull pack2(float a, float b) {
    ull r;
    asm("mov.b64 %0, {%1, %2};" : "=l"(r)
        : "r"(__float_as_uint(a)), "r"(__float_as_uint(b)));
    return r;
}
__device__ __forceinline__ float2 unpack2(ull v) {
    unsigned int lo, hi;
    asm("mov.b64 {%0, %1}, %2;" : "=r"(lo), "=r"(hi) : "l"(v));
    return make_float2(__uint_as_float(lo), __uint_as_float(hi));
}
__device__ __forceinline__ void bmerge(float v, int j,
    float& m0, float& m1, float& m2, int& i0, int& i1, int& i2) {
    bool p0 = v < m0, p1 = v < m1, p2 = v < m2;
    float nm2 = p1 ? m1 : (p2 ? v : m2);
    int   ni2 = p1 ? i1 : (p2 ? j : i2);
    float nm1 = p0 ? m0 : (p1 ? v : m1);
    int   ni1 = p0 ? i0 : (p1 ? j : i1);
    float nm0 = p0 ? v : m0;
    int   ni0 = p0 ? j : i0;
    m0 = nm0; m1 = nm1; m2 = nm2;
    i0 = ni0; i1 = ni1; i2 = ni2;
}

// ---------------------------------------------------------------------------
// Kernel 0: weight prep — permute + bf16 hi/lo split, [128][148]
// ---------------------------------------------------------------------------
#define WP_ITEMS (2 * 128 * WSTR)
#define WP_BLOCKS ((WP_ITEMS + 127) / 128)

__global__ void __launch_bounds__(128) wprep_kernel(
    const float* __restrict__ w1, const float* __restrict__ w2) {
    int i = blockIdx.x * 128 + threadIdx.x;
    if (i >= WP_ITEMS) return;
    int which = i / (128 * WSTR);
    int t = i % (128 * WSTR);
    int row = t / WSTR, col = t % WSTR;
    float v = 0.f;
    if (which == 0) {
        if (col < 128)      v = w1[row * INC + 3 + col];
        else if (col < 131) v = w1[row * INC + (col - 128)];
    } else {
        if (col < 128)      v = w2[row * 128 + col];
    }
    __nv_bfloat16 hi = __float2bfloat16_rn(v);
    __nv_bfloat16 lo = __float2bfloat16_rn(v - __bfloat162float(hi));
    if (which == 0) { g_w1h[t] = hi; g_w1l[t] = lo; }
    else            { g_w2h[t] = hi; g_w2l[t] = lo; }
}

// ---------------------------------------------------------------------------
// Kernel 1: kNN, 4-way M-split. 1024 blocks = 256 q-tiles x 4 quarters.
//   128 threads, 2 queries/thread, 512 key-pairs in 16KB smem,
//   two-pass flag-and-replay; exact partial top-3 per quarter.
// ---------------------------------------------------------------------------
__global__ void __launch_bounds__(128) knn_kernel(
    const float* __restrict__ x, const float* __restrict__ sx) {
    extern __shared__ float4 sm4[];
    float4* skA = sm4;         // 512 float4 = 8KB
    float4* skB = sm4 + MQ;    // 8KB

    const int quar = blockIdx.x & 3;
    const int q0   = (blockIdx.x >> 2) * 256;
    const int b    = q0 / NN;
    const int tid  = threadIdx.x;
    const int jbase = quar * (2 * MQ);

    const float* sxb = sx + (size_t)b * MM * 3 + (size_t)quar * MQ * 6;
    for (int j2 = tid; j2 < MQ; j2 += 128) {
        const float* p = sxb + (size_t)j2 * 6;
        float a0 = p[0], a1 = p[1], a2 = p[2];
        float c0 = p[3], c1 = p[4], c2 = p[5];
        skA[j2] = make_float4(-2.f * a0, -2.f * c0, -2.f * a1, -2.f * c1);
        skB[j2] = make_float4(-2.f * a2, -2.f * c2,
                              a0 * a0 + a1 * a1 + a2 * a2,
                              c0 * c0 + c1 * c1 + c2 * c2);
    }
    __syncthreads();

    const int qa = q0 + tid;
    const int qb = q0 + 128 + tid;
    float xa0 = x[qa * 3 + 0], xa1 = x[qa * 3 + 1], xa2 = x[qa * 3 + 2];
    float xb0 = x[qb * 3 + 0], xb1 = x[qb * 3 + 1], xb2 = x[qb * 3 + 2];
    const ull ax0 = pack2(xa0, xa0), ax1 = pack2(xa1, xa1), ax2 = pack2(xa2, xa2);
    const ull bx0 = pack2(xb0, xb0), bx1 = pack2(xb1, xb1), bx2 = pack2(xb2, xb2);

    const ulonglong2* A2 = (const ulonglong2*)skA;
    const ulonglong2* B2 = (const ulonglong2*)skB;

    // ---- pass 1: branchless chunk-min bound + flags (64 chunks = 2 words) ----
    float am0 = CUDART_INF_F, am1 = CUDART_INF_F, am2 = CUDART_INF_F;
    float bm0 = CUDART_INF_F, bm1 = CUDART_INF_F, bm2 = CUDART_INF_F;
    unsigned fa[2], fb[2];

#pragma unroll
    for (int w2 = 0; w2 < 2; w2++) {
        unsigned fma_ = 0, fmb_ = 0;
#pragma unroll 1
        for (int cb = 0; cb < 32; cb++) {
            const int jc = w2 * 256 + cb * 8;
            float pa[8], pb_[8];
#pragma unroll
            for (int u = 0; u < 8; u++) {
                ulonglong2 A  = A2[jc + u];
                ulonglong2 Bv = B2[jc + u];
                ull da = fma2(Bv.x, ax2, Bv.y);
                da = fma2(A.y, ax1, da);
                da = fma2(A.x, ax0, da);
                float2 va = unpack2(da);
                pa[u] = fminf(va.x, va.y);
                ull db = fma2(Bv.x, bx2, Bv.y);
                db = fma2(A.y, bx1, db);
                db = fma2(A.x, bx0, db);
                float2 vb = unpack2(db);
                pb_[u] = fminf(vb.x, vb.y);
            }
            float ca = fminf(fminf(fminf(pa[0], pa[1]), fminf(pa[2], pa[3])),
                             fminf(fminf(pa[4], pa[5]), fminf(pa[6], pa[7])));
            float cbv = fminf(fminf(fminf(pb_[0], pb_[1]), fminf(pb_[2], pb_[3])),
                              fminf(fminf(pb_[4], pb_[5]), fminf(pb_[6], pb_[7])));
            fma_ |= (ca  <= am2) ? (1u << cb) : 0u;
            fmb_ |= (cbv <= bm2) ? (1u << cb) : 0u;
            am2 = fminf(am2, fmaxf(am1, ca));
            am1 = fminf(am1, fmaxf(am0, ca));
            am0 = fminf(am0, ca);
            bm2 = fminf(bm2, fmaxf(bm1, cbv));
            bm1 = fminf(bm1, fmaxf(bm0, cbv));
            bm0 = fminf(bm0, cbv);
        }
        fa[w2] = fma_;
        fb[w2] = fmb_;
    }

    // ---- pass 2: replay flagged chunks ----
    const size_t pbase = (size_t)quar * NQ * 3;
    {
        float n0 = CUDART_INF_F, n1 = CUDART_INF_F, n2 = CUDART_INF_F;
        int   i0 = 0, i1 = 0, i2 = 0;
#pragma unroll
        for (int w2 = 0; w2 < 2; w2++) {
            unsigned fm = fa[w2];
            while (fm) {
                const int cb = __ffs(fm) - 1;
                fm &= fm - 1;
                const int jc = w2 * 256 + cb * 8;
#pragma unroll
                for (int u = 0; u < 8; u++) {
                    ulonglong2 A  = A2[jc + u];
                    ulonglong2 Bv = B2[jc + u];
                    ull d = fma2(Bv.x, ax2, Bv.y);
                    d = fma2(A.y, ax1, d);
                    d = fma2(A.x, ax0, d);
                    float2 vv = unpack2(d);
                    bmerge(vv.x, jbase + 2 * (jc + u),     n0, n1, n2, i0, i1, i2);
                    bmerge(vv.y, jbase + 2 * (jc + u) + 1, n0, n1, n2, i0, i1, i2);
                }
            }
        }
        g_pv[pbase + qa * 3 + 0] = n0; g_pi[pbase + qa * 3 + 0] = i0;
        g_pv[pbase + qa * 3 + 1] = n1; g_pi[pbase + qa * 3 + 1] = i1;
        g_pv[pbase + qa * 3 + 2] = n2; g_pi[pbase + qa * 3 + 2] = i2;
    }
    {
        float n0 = CUDART_INF_F, n1 = CUDART_INF_F, n2 = CUDART_INF_F;
        int   i0 = 0, i1 = 0, i2 = 0;
#pragma unroll
        for (int w2 = 0; w2 < 2; w2++) {
            unsigned fm = fb[w2];
            while (fm) {
                const int cb = __ffs(fm) - 1;
                fm &= fm - 1;
                const int jc = w2 * 256 + cb * 8;
#pragma unroll
                for (int u = 0; u < 8; u++) {
                    ulonglong2 A  = A2[jc + u];
                    ulonglong2 Bv = B2[jc + u];
                    ull d = fma2(Bv.x, bx2, Bv.y);
                    d = fma2(A.y, bx1, d);
                    d = fma2(A.x, bx0, d);
                    float2 vv = unpack2(d);
                    bmerge(vv.x, jbase + 2 * (jc + u),     n0, n1, n2, i0, i1, i2);
                    bmerge(vv.y, jbase + 2 * (jc + u) + 1, n0, n1, n2, i0, i1, i2);
                }
            }
        }
        g_pv[pbase + qb * 3 + 0] = n0; g_pi[pbase + qb * 3 + 0] = i0;
        g_pv[pbase + qb * 3 + 1] = n1; g_pi[pbase + qb * 3 + 1] = i1;
        g_pv[pbase + qb * 3 + 2] = n2; g_pi[pbase + qb * 3 + 2] = i2;
    }
}

// ---------------------------------------------------------------------------
// Kernel 1b: merge the 4 candidate-quarter partials -> g_idx
//   quarters ascend in index; strict-< merge preserves tie order.
// ---------------------------------------------------------------------------
__global__ void __launch_bounds__(256) merge_kernel() {
    int q = blockIdx.x * 256 + threadIdx.x;
    if (q >= NQ) return;
    float m0 = g_pv[q * 3 + 0], m1 = g_pv[q * 3 + 1], m2 = g_pv[q * 3 + 2];
    int   i0 = g_pi[q * 3 + 0], i1 = g_pi[q * 3 + 1], i2 = g_pi[q * 3 + 2];
#pragma unroll
    for (int h = 1; h < NSPLIT; h++) {
        const size_t o = (size_t)h * NQ * 3;
#pragma unroll
        for (int k = 0; k < 3; k++)
            bmerge(g_pv[o + q * 3 + k], g_pi[o + q * 3 + k], m0, m1, m2, i0, i1, i2);
    }
    g_idx[q * 3 + 0] = i0;
    g_idx[q * 3 + 1] = i1;
    g_idx[q * 3 + 2] = i2;
}

// ---------------------------------------------------------------------------
// Kernel 2: WMMA bf16-split MLP, 64-point tile, 2 blocks/SM, WSTR=148.
// ---------------------------------------------------------------------------
#define SM_AH   0
#define SM_AL   (SM_AH + MTILE * WSTR * 2)     // 18944
#define SM_WH   (SM_AL + MTILE * WSTR * 2)     // 37888
#define SM_WL   (SM_WH + 128 * WSTR * 2)       // 75776
#define SM_BIAS (SM_WL + 128 * WSTR * 2)       // 113664
#define MLP_SMEM (SM_BIAS + 1024)              // 114688

__global__ void __launch_bounds__(256, 2) mlp_wmma_kernel(
    const float* __restrict__ x, const float* __restrict__ feat,
    const float* __restrict__ b1, const float* __restrict__ b2,
    float* __restrict__ out) {
    extern __shared__ char smc[];
    __nv_bfloat16* AH = (__nv_bfloat16*)(smc + SM_AH);
    __nv_bfloat16* AL = (__nv_bfloat16*)(smc + SM_AL);
    __nv_bfloat16* WH = (__nv_bfloat16*)(smc + SM_WH);
    __nv_bfloat16* WL = (__nv_bfloat16*)(smc + SM_WL);
    float*         Cf = (float*)(smc + SM_WH);          // 64*132*4 < WH size
    float*         b1s = (float*)(smc + SM_BIAS);
    float*         b2s = b1s + 128;

    const int tid  = threadIdx.x;
    const int wid  = tid >> 5;
    const int lane = tid & 31;
    const int ms   = wid & 3;
    const int nh   = wid >> 2;
    const int p0   = blockIdx.x * MTILE;
    const int b    = p0 / NN;
    const int n0   = p0 - b * NN;

    // ---- zero A + stage biases + load W1 ----
    {
        uint4 z = make_uint4(0, 0, 0, 0);
        for (int i = tid; i < MTILE * WSTR * 4 / 16; i += 256)
            *(uint4*)(smc + SM_AH + i * 16) = z;
        if (tid < 128) { b1s[tid] = b1[tid]; b2s[tid] = b2[tid]; }
        const uint4* s1 = (const uint4*)g_w1h;
        const uint4* s2 = (const uint4*)g_w1l;
        for (int i = tid; i < 128 * WSTR * 2 / 16; i += 256) {
            *(uint4*)(smc + SM_WH + i * 16) = s1[i];
            *(uint4*)(smc + SM_WL + i * 16) = s2[i];
        }
    }
    __syncthreads();

    // ---- gather + bf16 split into AH/AL (8 warps x 8 points) ----
    {
        const float4* F = (const float4*)feat;
#pragma unroll 1
        for (int t = 0; t < 8; t++) {
            const int pt = wid * 8 + t;
            const int gq = p0 + pt;
            const int j0 = g_idx[gq * 3 + 0];
            const int j1 = g_idx[gq * 3 + 1];
            const int j2 = g_idx[gq * 3 + 2];
            float4 f0 = F[(size_t)(b * MM + j0) * 32 + lane];
            float4 f1 = F[(size_t)(b * MM + j1) * 32 + lane];
            float4 f2 = F[(size_t)(b * MM + j2) * 32 + lane];
            float v[4];
            v[0] = (f0.x + f1.x + f2.x) * (1.f / 3.f);
            v[1] = (f0.y + f1.y + f2.y) * (1.f / 3.f);
            v[2] = (f0.z + f1.z + f2.z) * (1.f / 3.f);
            v[3] = (f0.w + f1.w + f2.w) * (1.f / 3.f);
            uint hw[2], lw[2];
#pragma unroll
            for (int q = 0; q < 2; q++) {
                __nv_bfloat16 h0 = __float2bfloat16_rn(v[2 * q]);
                __nv_bfloat16 h1 = __float2bfloat16_rn(v[2 * q + 1]);
                __nv_bfloat16 l0 = __float2bfloat16_rn(v[2 * q] - __bfloat162float(h0));
                __nv_bfloat16 l1 = __float2bfloat16_rn(v[2 * q + 1] - __bfloat162float(h1));
                hw[q] = (uint)__bfloat16_as_ushort(h0) | ((uint)__bfloat16_as_ushort(h1) << 16);
                lw[q] = (uint)__bfloat16_as_ushort(l0) | ((uint)__bfloat16_as_ushort(l1) << 16);
            }
            *(uint2*)&AH[pt * WSTR + 4 * lane] = make_uint2(hw[0], hw[1]);
            *(uint2*)&AL[pt * WSTR + 4 * lane] = make_uint2(lw[0], lw[1]);
            if (lane == 0) {
                float c0 = x[gq * 3 + 0], c1 = x[gq * 3 + 1], c2 = x[gq * 3 + 2];
                __nv_bfloat16 h0 = __float2bfloat16_rn(c0);
                __nv_bfloat16 h1 = __float2bfloat16_rn(c1);
                __nv_bfloat16 h2 = __float2bfloat16_rn(c2);
                __nv_bfloat16 l0 = __float2bfloat16_rn(c0 - __bfloat162float(h0));
                __nv_bfloat16 l1 = __float2bfloat16_rn(c1 - __bfloat162float(h1));
                __nv_bfloat16 l2 = __float2bfloat16_rn(c2 - __bfloat162float(h2));
                *(uint2*)&AH[pt * WSTR + 128] = make_uint2(
                    (uint)__bfloat16_as_ushort(h0) | ((uint)__bfloat16_as_ushort(h1) << 16),
                    (uint)__bfloat16_as_ushort(h2));
                *(uint2*)&AL[pt * WSTR + 128] = make_uint2(
                    (uint)__bfloat16_as_ushort(l0) | ((uint)__bfloat16_as_ushort(l1) << 16),
                    (uint)__bfloat16_as_ushort(l2));
            }
        }
    }
    __syncthreads();

    wmma::fragment<wmma::accumulator, 16, 16, 16, float> acc[4];
    wmma::fragment<wmma::matrix_a, 16, 16, 16, __nv_bfloat16, wmma::row_major> ah, al;
    wmma::fragment<wmma::matrix_b, 16, 16, 16, __nv_bfloat16, wmma::col_major> bh, bl;
    const int m0 = ms * 16;

    // ---- layer 1: K=144 (9 kt) ----
#pragma unroll
    for (int nt = 0; nt < 4; nt++) wmma::fill_fragment(acc[nt], 0.f);
#pragma unroll 1
    for (int kt = 0; kt < 9; kt++) {
        wmma::load_matrix_sync(ah, AH + m0 * WSTR + kt * 16, WSTR);
        wmma::load_matrix_sync(al, AL + m0 * WSTR + kt * 16, WSTR);
#pragma unroll
        for (int nt = 0; nt < 4; nt++) {
            const int n = nh * 4 + nt;
            wmma::load_matrix_sync(bh, WH + n * 16 * WSTR + kt * 16, WSTR);
            wmma::load_matrix_sync(bl, WL + n * 16 * WSTR + kt * 16, WSTR);
            wmma::mma_sync(acc[nt], ah, bh, acc[nt]);
            wmma::mma_sync(acc[nt], al, bh, acc[nt]);
            wmma::mma_sync(acc[nt], ah, bl, acc[nt]);
        }
    }
    __syncthreads();

    // ---- epilogue 1 ----
#pragma unroll
    for (int nt = 0; nt < 4; nt++)
        wmma::store_matrix_sync(Cf + m0 * CSTR + nh * 64 + nt * 16, acc[nt], CSTR,
                                wmma::mem_row_major);
    __syncthreads();
#pragma unroll 1
    for (int idx = tid; idx < 64 * 64; idx += 256) {
        const int m = idx >> 6;
        const int c = (idx & 63) * 2;
        float v0 = fmaxf(Cf[m * CSTR + c]     + b1s[c],     0.f);
        float v1 = fmaxf(Cf[m * CSTR + c + 1] + b1s[c + 1], 0.f);
        __nv_bfloat16 h0 = __float2bfloat16_rn(v0);
        __nv_bfloat16 h1 = __float2bfloat16_rn(v1);
        __nv_bfloat16 l0 = __float2bfloat16_rn(v0 - __bfloat162float(h0));
        __nv_bfloat16 l1 = __float2bfloat16_rn(v1 - __bfloat162float(h1));
        *(uint*)&AH[m * WSTR + c] =
            (uint)__bfloat16_as_ushort(h0) | ((uint)__bfloat16_as_ushort(h1) << 16);
        *(uint*)&AL[m * WSTR + c] =
            (uint)__bfloat16_as_ushort(l0) | ((uint)__bfloat16_as_ushort(l1) << 16);
    }
    __syncthreads();

    {
        const uint4* s1 = (const uint4*)g_w2h;
        const uint4* s2 = (const uint4*)g_w2l;
        for (int i = tid; i < 128 * WSTR * 2 / 16; i += 256) {
            *(uint4*)(smc + SM_WH + i * 16) = s1[i];
            *(uint4*)(smc + SM_WL + i * 16) = s2[i];
        }
    }
    __syncthreads();

    // ---- layer 2: K=128 (8 kt) ----
#pragma unroll
    for (int nt = 0; nt < 4; nt++) wmma::fill_fragment(acc[nt], 0.f);
#pragma unroll 1
    for (int kt = 0; kt < 8; kt++) {
        wmma::load_matrix_sync(ah, AH + m0 * WSTR + kt * 16, WSTR);
        wmma::load_matrix_sync(al, AL + m0 * WSTR + kt * 16, WSTR);
#pragma unroll
        for (int nt = 0; nt < 4; nt++) {
            const int n = nh * 4 + nt;
            wmma::load_matrix_sync(bh, WH + n * 16 * WSTR + kt * 16, WSTR);
            wmma::load_matrix_sync(bl, WL + n * 16 * WSTR + kt * 16, WSTR);
            wmma::mma_sync(acc[nt], ah, bh, acc[nt]);
            wmma::mma_sync(acc[nt], al, bh, acc[nt]);
            wmma::mma_sync(acc[nt], ah, bl, acc[nt]);
        }
    }
    __syncthreads();

    // ---- epilogue 2 ----
#pragma unroll
    for (int nt = 0; nt < 4; nt++)
        wmma::store_matrix_sync(Cf + m0 * CSTR + nh * 64 + nt * 16, acc[nt], CSTR,
                                wmma::mem_row_major);
    __syncthreads();
    {
        float* ob = out + (size_t)b * OUTC * NN + n0;
        for (int idx = tid; idx < 128 * 64; idx += 256) {
            const int c = idx >> 6;
            const int m = idx & 63;
            ob[(size_t)c * NN + m] = Cf[m * CSTR + c] + b2s[c];
        }
    }
}

// ---------------------------------------------------------------------------
extern "C" void kernel_launch(void* const* d_in, const int* in_sizes, int n_in,
                              void* d_out, int out_size) {
    const float* x   = (const float*)d_in[0];
    const float* sx  = (const float*)d_in[1];
    const float* ft  = (const float*)d_in[2];
    const float* w1  = (const float*)d_in[3];
    const float* b1  = (const float*)d_in[4];
    const float* w2  = (const float*)d_in[5];
    const float* b2  = (const float*)d_in[6];
    float* out = (float*)d_out;

    const int knn_smem = 2 * MQ * sizeof(float4);   // 16 KB

    cudaFuncSetAttribute(knn_kernel,
                         cudaFuncAttributeMaxDynamicSharedMemorySize, knn_smem);
    cudaFuncSetAttribute(mlp_wmma_kernel,
                         cudaFuncAttributeMaxDynamicSharedMemorySize, MLP_SMEM);

    wprep_kernel<<<WP_BLOCKS, 128>>>(w1, w2);
    knn_kernel<<<(NQ / 256) * NSPLIT, 128, knn_smem>>>(x, sx);
    merge_kernel<<<NQ / 256, 256>>>();
    mlp_wmma_kernel<<<NQ / MTILE, 256, MLP_SMEM>>>(x, ft, b1, b2, out);
}

// round 15
// speedup vs baseline: 1.0810x; 1.0810x over previous
#include <cuda_runtime.h>
#include <cuda_bf16.h>
#include <math_constants.h>
#include <mma.h>

using namespace nvcuda;

#define BB 2
#define NN 32768
#define NQ (BB * NN)
#define MM 4096
#define MH 1024          // pairs per candidate half
#define NSPLIT 2
#define CC 128
#define OUTC 128
#define INC 131
#define MTILE 64

#define WSTR 144         // bf16 row stride == K1
#define CSTR 132

typedef unsigned long long ull;
typedef unsigned int uint;

// ---------------------------------------------------------------------------
// Scratch (__device__ globals)
// ---------------------------------------------------------------------------
__device__ __align__(16) __nv_bfloat16 g_w1h[128 * WSTR];
__device__ __align__(16) __nv_bfloat16 g_w1l[128 * WSTR];
__device__ __align__(16) __nv_bfloat16 g_w2h[128 * WSTR];
__device__ __align__(16) __nv_bfloat16 g_w2l[128 * WSTR];
__device__ int g_idx[NQ * 3];
__device__ float g_pv[NSPLIT * NQ * 3];
__device__ int   g_pi[NSPLIT * NQ * 3];

// ---------------------------------------------------------------------------
// helpers
// ---------------------------------------------------------------------------
__device__ __forceinline__ ull fma2(ull a, ull b, ull c) {
    ull d;
    asm("fma.rn.f32x2 %0, %1, %2, %3;" : "=l"(d) : "l"(a), "l"(b), "l"(c));
    return d;
}
__device__ __forceinline__ ull pack2(float a, float b) {
    ull r;
    asm("mov.b64 %0, {%1, %2};" : "=l"(r)
        : "r"(__float_as_uint(a)), "r"(__float_as_uint(b)));
    return r;
}
__device__ __forceinline__ float2 unpack2(ull v) {
    unsigned int lo, hi;
    asm("mov.b64 {%0, %1}, %2;" : "=r"(lo), "=r"(hi) : "l"(v));
    return make_float2(__uint_as_float(lo), __uint_as_float(hi));
}
__device__ __forceinline__ void bmerge(float v, int j,
    float& m0, float& m1, float& m2, int& i0, int& i1, int& i2) {
    bool p0 = v < m0, p1 = v < m1, p2 = v < m2;
    float nm2 = p1 ? m1 : (p2 ? v : m2);
    int   ni2 = p1 ? i1 : (p2 ? j : i2);
    float nm1 = p0 ? m0 : (p1 ? v : m1);
    int   ni1 = p0 ? i0 : (p1 ? j : i1);
    float nm0 = p0 ? v : m0;
    int   ni0 = p0 ? j : i0;
    m0 = nm0; m1 = nm1; m2 = nm2;
    i0 = ni0; i1 = ni1; i2 = ni2;
}

// ---------------------------------------------------------------------------
// Kernel 0: weight prep — permute + bf16 hi/lo split, [128][144]
// ---------------------------------------------------------------------------
#define WP_ITEMS (2 * 128 * WSTR)
#define WP_BLOCKS ((WP_ITEMS + 127) / 128)

__global__ void __launch_bounds__(128) wprep_kernel(
    const float* __restrict__ w1, const float* __restrict__ w2) {
    int i = blockIdx.x * 128 + threadIdx.x;
    if (i >= WP_ITEMS) return;
    int which = i / (128 * WSTR);
    int t = i % (128 * WSTR);
    int row = t / WSTR, col = t % WSTR;
    float v = 0.f;
    if (which == 0) {
        if (col < 128)      v = w1[row * INC + 3 + col];
        else if (col < 131) v = w1[row * INC + (col - 128)];
    } else {
        if (col < 128)      v = w2[row * 128 + col];
    }
    __nv_bfloat16 hi = __float2bfloat16_rn(v);
    __nv_bfloat16 lo = __float2bfloat16_rn(v - __bfloat162float(hi));
    if (which == 0) { g_w1h[t] = hi; g_w1l[t] = lo; }
    else            { g_w2h[t] = hi; g_w2l[t] = lo; }
}

// ---------------------------------------------------------------------------
// Kernel 1: kNN, 2-way M-split (reverted to R13 config — known good)
// ---------------------------------------------------------------------------
__global__ void __launch_bounds__(128) knn_kernel(
    const float* __restrict__ x, const float* __restrict__ sx) {
    extern __shared__ float4 sm4[];
    float4* skA = sm4;
    float4* skB = sm4 + MH;

    const int half = blockIdx.x & 1;
    const int q0   = (blockIdx.x >> 1) * 256;
    const int b    = q0 / NN;
    const int tid  = threadIdx.x;
    const int jbase = half * (2 * MH);

    const float* sxb = sx + (size_t)b * MM * 3 + (size_t)half * MH * 6;
    for (int j2 = tid; j2 < MH; j2 += 128) {
        const float* p = sxb + (size_t)j2 * 6;
        float a0 = p[0], a1 = p[1], a2 = p[2];
        float c0 = p[3], c1 = p[4], c2 = p[5];
        skA[j2] = make_float4(-2.f * a0, -2.f * c0, -2.f * a1, -2.f * c1);
        skB[j2] = make_float4(-2.f * a2, -2.f * c2,
                              a0 * a0 + a1 * a1 + a2 * a2,
                              c0 * c0 + c1 * c1 + c2 * c2);
    }
    __syncthreads();

    const int qa = q0 + tid;
    const int qb = q0 + 128 + tid;
    float xa0 = x[qa * 3 + 0], xa1 = x[qa * 3 + 1], xa2 = x[qa * 3 + 2];
    float xb0 = x[qb * 3 + 0], xb1 = x[qb * 3 + 1], xb2 = x[qb * 3 + 2];
    const ull ax0 = pack2(xa0, xa0), ax1 = pack2(xa1, xa1), ax2 = pack2(xa2, xa2);
    const ull bx0 = pack2(xb0, xb0), bx1 = pack2(xb1, xb1), bx2 = pack2(xb2, xb2);

    const ulonglong2* A2 = (const ulonglong2*)skA;
    const ulonglong2* B2 = (const ulonglong2*)skB;

    float am0 = CUDART_INF_F, am1 = CUDART_INF_F, am2 = CUDART_INF_F;
    float bm0 = CUDART_INF_F, bm1 = CUDART_INF_F, bm2 = CUDART_INF_F;
    unsigned fa[4], fb[4];

#pragma unroll
    for (int w4 = 0; w4 < 4; w4++) {
        unsigned fma_ = 0, fmb_ = 0;
#pragma unroll 1
        for (int cb = 0; cb < 32; cb++) {
            const int jc = w4 * 256 + cb * 8;
            float pa[8], pb_[8];
#pragma unroll
            for (int u = 0; u < 8; u++) {
                ulonglong2 A  = A2[jc + u];
                ulonglong2 Bv = B2[jc + u];
                ull da = fma2(Bv.x, ax2, Bv.y);
                da = fma2(A.y, ax1, da);
                da = fma2(A.x, ax0, da);
                float2 va = unpack2(da);
                pa[u] = fminf(va.x, va.y);
                ull db = fma2(Bv.x, bx2, Bv.y);
                db = fma2(A.y, bx1, db);
                db = fma2(A.x, bx0, db);
                float2 vb = unpack2(db);
                pb_[u] = fminf(vb.x, vb.y);
            }
            float ca = fminf(fminf(fminf(pa[0], pa[1]), fminf(pa[2], pa[3])),
                             fminf(fminf(pa[4], pa[5]), fminf(pa[6], pa[7])));
            float cbv = fminf(fminf(fminf(pb_[0], pb_[1]), fminf(pb_[2], pb_[3])),
                              fminf(fminf(pb_[4], pb_[5]), fminf(pb_[6], pb_[7])));
            fma_ |= (ca  <= am2) ? (1u << cb) : 0u;
            fmb_ |= (cbv <= bm2) ? (1u << cb) : 0u;
            am2 = fminf(am2, fmaxf(am1, ca));
            am1 = fminf(am1, fmaxf(am0, ca));
            am0 = fminf(am0, ca);
            bm2 = fminf(bm2, fmaxf(bm1, cbv));
            bm1 = fminf(bm1, fmaxf(bm0, cbv));
            bm0 = fminf(bm0, cbv);
        }
        fa[w4] = fma_;
        fb[w4] = fmb_;
    }

    const size_t pbase = (size_t)half * NQ * 3;
    {
        float n0 = CUDART_INF_F, n1 = CUDART_INF_F, n2 = CUDART_INF_F;
        int   i0 = 0, i1 = 0, i2 = 0;
#pragma unroll
        for (int w4 = 0; w4 < 4; w4++) {
            unsigned fm = fa[w4];
            while (fm) {
                const int cb = __ffs(fm) - 1;
                fm &= fm - 1;
                const int jc = w4 * 256 + cb * 8;
#pragma unroll
                for (int u = 0; u < 8; u++) {
                    ulonglong2 A  = A2[jc + u];
                    ulonglong2 Bv = B2[jc + u];
                    ull d = fma2(Bv.x, ax2, Bv.y);
                    d = fma2(A.y, ax1, d);
                    d = fma2(A.x, ax0, d);
                    float2 vv = unpack2(d);
                    bmerge(vv.x, jbase + 2 * (jc + u),     n0, n1, n2, i0, i1, i2);
                    bmerge(vv.y, jbase + 2 * (jc + u) + 1, n0, n1, n2, i0, i1, i2);
                }
            }
        }
        g_pv[pbase + qa * 3 + 0] = n0; g_pi[pbase + qa * 3 + 0] = i0;
        g_pv[pbase + qa * 3 + 1] = n1; g_pi[pbase + qa * 3 + 1] = i1;
        g_pv[pbase + qa * 3 + 2] = n2; g_pi[pbase + qa * 3 + 2] = i2;
    }
    {
        float n0 = CUDART_INF_F, n1 = CUDART_INF_F, n2 = CUDART_INF_F;
        int   i0 = 0, i1 = 0, i2 = 0;
#pragma unroll
        for (int w4 = 0; w4 < 4; w4++) {
            unsigned fm = fb[w4];
            while (fm) {
                const int cb = __ffs(fm) - 1;
                fm &= fm - 1;
                const int jc = w4 * 256 + cb * 8;
#pragma unroll
                for (int u = 0; u < 8; u++) {
                    ulonglong2 A  = A2[jc + u];
                    ulonglong2 Bv = B2[jc + u];
                    ull d = fma2(Bv.x, bx2, Bv.y);
                    d = fma2(A.y, bx1, d);
                    d = fma2(A.x, bx0, d);
                    float2 vv = unpack2(d);
                    bmerge(vv.x, jbase + 2 * (jc + u),     n0, n1, n2, i0, i1, i2);
                    bmerge(vv.y, jbase + 2 * (jc + u) + 1, n0, n1, n2, i0, i1, i2);
                }
            }
        }
        g_pv[pbase + qb * 3 + 0] = n0; g_pi[pbase + qb * 3 + 0] = i0;
        g_pv[pbase + qb * 3 + 1] = n1; g_pi[pbase + qb * 3 + 1] = i1;
        g_pv[pbase + qb * 3 + 2] = n2; g_pi[pbase + qb * 3 + 2] = i2;
    }
}

// ---------------------------------------------------------------------------
// Kernel 1b: merge candidate-half partials -> g_idx
// ---------------------------------------------------------------------------
__global__ void __launch_bounds__(256) merge_kernel() {
    int q = blockIdx.x * 256 + threadIdx.x;
    if (q >= NQ) return;
    float m0 = g_pv[q * 3 + 0], m1 = g_pv[q * 3 + 1], m2 = g_pv[q * 3 + 2];
    int   i0 = g_pi[q * 3 + 0], i1 = g_pi[q * 3 + 1], i2 = g_pi[q * 3 + 2];
    const size_t o = (size_t)NQ * 3;
#pragma unroll
    for (int k = 0; k < 3; k++)
        bmerge(g_pv[o + q * 3 + k], g_pi[o + q * 3 + k], m0, m1, m2, i0, i1, i2);
    g_idx[q * 3 + 0] = i0;
    g_idx[q * 3 + 1] = i1;
    g_idx[q * 3 + 2] = i2;
}

// ---------------------------------------------------------------------------
// Kernel 2: WMMA bf16-split MLP, W-phase split for 3 blocks/SM.
//   SMEM: AH(18KB) | AL(18KB) | W(36KB, restaged 4x) | bias -> 73KB/block.
//   Phase A (W=Wh): acc += Ah*Bh + Al*Bh (shared bh fragment)
//   Phase B (W=Wl): acc += Ah*Bl
// ---------------------------------------------------------------------------
#define SM_AH   0
#define SM_AL   (SM_AH + MTILE * WSTR * 2)   // 18432
#define SM_W    (SM_AL + MTILE * WSTR * 2)   // 36864
#define SM_BIAS (SM_W + 128 * WSTR * 2)      // 73728
#define MLP_SMEM (SM_BIAS + 1024)            // 74752

__device__ __forceinline__ void stage_w(char* smc, const __nv_bfloat16* src, int tid) {
    const uint4* s = (const uint4*)src;
#pragma unroll
    for (int r = 0; r < 9; r++) {
        int i = tid + r * 256;
        *(uint4*)(smc + SM_W + i * 16) = s[i];
    }
}

__global__ void __launch_bounds__(256, 3) mlp_wmma_kernel(
    const float* __restrict__ x, const float* __restrict__ feat,
    const float* __restrict__ b1, const float* __restrict__ b2,
    float* __restrict__ out) {
    extern __shared__ char smc[];
    __nv_bfloat16* AH = (__nv_bfloat16*)(smc + SM_AH);
    __nv_bfloat16* AL = (__nv_bfloat16*)(smc + SM_AL);
    __nv_bfloat16* WB = (__nv_bfloat16*)(smc + SM_W);
    float*         Cf = (float*)(smc + SM_W);      // 64*132*4 = 33792 <= 36864
    float*         b1s = (float*)(smc + SM_BIAS);
    float*         b2s = b1s + 128;

    const int tid  = threadIdx.x;
    const int wid  = tid >> 5;
    const int lane = tid & 31;
    const int ms   = wid & 3;       // m-strip (16 rows)
    const int nh   = wid >> 2;      // n-half (64 cols)
    const int p0   = blockIdx.x * MTILE;
    const int b    = p0 / NN;
    const int n0   = p0 - b * NN;

    // ---- zero A + stage biases + stage W1h ----
    {
        uint4 z = make_uint4(0, 0, 0, 0);
        for (int i = tid; i < MTILE * WSTR * 4 / 16; i += 256)
            *(uint4*)(smc + SM_AH + i * 16) = z;
        if (tid < 128) { b1s[tid] = b1[tid]; b2s[tid] = b2[tid]; }
        stage_w(smc, g_w1h, tid);
    }
    __syncthreads();

    // ---- gather + bf16 split into AH/AL (8 warps x 8 points) ----
    {
        const float4* F = (const float4*)feat;
#pragma unroll 1
        for (int t = 0; t < 8; t++) {
            const int pt = wid * 8 + t;
            const int gq = p0 + pt;
            const int j0 = g_idx[gq * 3 + 0];
            const int j1 = g_idx[gq * 3 + 1];
            const int j2 = g_idx[gq * 3 + 2];
            float4 f0 = F[(size_t)(b * MM + j0) * 32 + lane];
            float4 f1 = F[(size_t)(b * MM + j1) * 32 + lane];
            float4 f2 = F[(size_t)(b * MM + j2) * 32 + lane];
            float v[4];
            v[0] = (f0.x + f1.x + f2.x) * (1.f / 3.f);
            v[1] = (f0.y + f1.y + f2.y) * (1.f / 3.f);
            v[2] = (f0.z + f1.z + f2.z) * (1.f / 3.f);
            v[3] = (f0.w + f1.w + f2.w) * (1.f / 3.f);
            uint hw[2], lw[2];
#pragma unroll
            for (int q = 0; q < 2; q++) {
                __nv_bfloat16 h0 = __float2bfloat16_rn(v[2 * q]);
                __nv_bfloat16 h1 = __float2bfloat16_rn(v[2 * q + 1]);
                __nv_bfloat16 l0 = __float2bfloat16_rn(v[2 * q] - __bfloat162float(h0));
                __nv_bfloat16 l1 = __float2bfloat16_rn(v[2 * q + 1] - __bfloat162float(h1));
                hw[q] = (uint)__bfloat16_as_ushort(h0) | ((uint)__bfloat16_as_ushort(h1) << 16);
                lw[q] = (uint)__bfloat16_as_ushort(l0) | ((uint)__bfloat16_as_ushort(l1) << 16);
            }
            *(uint2*)&AH[pt * WSTR + 4 * lane] = make_uint2(hw[0], hw[1]);
            *(uint2*)&AL[pt * WSTR + 4 * lane] = make_uint2(lw[0], lw[1]);
            if (lane == 0) {
                float c0 = x[gq * 3 + 0], c1 = x[gq * 3 + 1], c2 = x[gq * 3 + 2];
                __nv_bfloat16 h0 = __float2bfloat16_rn(c0);
                __nv_bfloat16 h1 = __float2bfloat16_rn(c1);
                __nv_bfloat16 h2 = __float2bfloat16_rn(c2);
                __nv_bfloat16 l0 = __float2bfloat16_rn(c0 - __bfloat162float(h0));
                __nv_bfloat16 l1 = __float2bfloat16_rn(c1 - __bfloat162float(h1));
                __nv_bfloat16 l2 = __float2bfloat16_rn(c2 - __bfloat162float(h2));
                *(uint2*)&AH[pt * WSTR + 128] = make_uint2(
                    (uint)__bfloat16_as_ushort(h0) | ((uint)__bfloat16_as_ushort(h1) << 16),
                    (uint)__bfloat16_as_ushort(h2));
                *(uint2*)&AL[pt * WSTR + 128] = make_uint2(
                    (uint)__bfloat16_as_ushort(l0) | ((uint)__bfloat16_as_ushort(l1) << 16),
                    (uint)__bfloat16_as_ushort(l2));
            }
        }
    }
    __syncthreads();

    wmma::fragment<wmma::accumulator, 16, 16, 16, float> acc[4];
    wmma::fragment<wmma::matrix_a, 16, 16, 16, __nv_bfloat16, wmma::row_major> ah, al;
    wmma::fragment<wmma::matrix_b, 16, 16, 16, __nv_bfloat16, wmma::col_major> bf;
    const int m0 = ms * 16;

    // ================= layer 1 (K=144, 9 kt) =================
#pragma unroll
    for (int nt = 0; nt < 4; nt++) wmma::fill_fragment(acc[nt], 0.f);

    // phase A: W = W1h -> acc += Ah*Bh + Al*Bh
#pragma unroll 1
    for (int kt = 0; kt < 9; kt++) {
        wmma::load_matrix_sync(ah, AH + m0 * WSTR + kt * 16, WSTR);
        wmma::load_matrix_sync(al, AL + m0 * WSTR + kt * 16, WSTR);
#pragma unroll
        for (int nt = 0; nt < 4; nt++) {
            const int n = nh * 4 + nt;
            wmma::load_matrix_sync(bf, WB + n * 16 * WSTR + kt * 16, WSTR);
            wmma::mma_sync(acc[nt], ah, bf, acc[nt]);
            wmma::mma_sync(acc[nt], al, bf, acc[nt]);
        }
    }
    __syncthreads();
    stage_w(smc, g_w1l, tid);
    __syncthreads();

    // phase B: W = W1l -> acc += Ah*Bl
#pragma unroll 1
    for (int kt = 0; kt < 9; kt++) {
        wmma::load_matrix_sync(ah, AH + m0 * WSTR + kt * 16, WSTR);
#pragma unroll
        for (int nt = 0; nt < 4; nt++) {
            const int n = nh * 4 + nt;
            wmma::load_matrix_sync(bf, WB + n * 16 * WSTR + kt * 16, WSTR);
            wmma::mma_sync(acc[nt], ah, bf, acc[nt]);
        }
    }
    __syncthreads();   // W dead -> Cf may overwrite

    // ---- epilogue 1: acc -> Cf -> bias+relu -> split -> AH/AL ----
#pragma unroll
    for (int nt = 0; nt < 4; nt++)
        wmma::store_matrix_sync(Cf + m0 * CSTR + nh * 64 + nt * 16, acc[nt], CSTR,
                                wmma::mem_row_major);
    __syncthreads();
#pragma unroll 1
    for (int idx = tid; idx < 64 * 64; idx += 256) {
        const int m = idx >> 6;
        const int c = (idx & 63) * 2;
        float v0 = fmaxf(Cf[m * CSTR + c]     + b1s[c],     0.f);
        float v1 = fmaxf(Cf[m * CSTR + c + 1] + b1s[c + 1], 0.f);
        __nv_bfloat16 h0 = __float2bfloat16_rn(v0);
        __nv_bfloat16 h1 = __float2bfloat16_rn(v1);
        __nv_bfloat16 l0 = __float2bfloat16_rn(v0 - __bfloat162float(h0));
        __nv_bfloat16 l1 = __float2bfloat16_rn(v1 - __bfloat162float(h1));
        *(uint*)&AH[m * WSTR + c] =
            (uint)__bfloat16_as_ushort(h0) | ((uint)__bfloat16_as_ushort(h1) << 16);
        *(uint*)&AL[m * WSTR + c] =
            (uint)__bfloat16_as_ushort(l0) | ((uint)__bfloat16_as_ushort(l1) << 16);
    }
    __syncthreads();   // Cf dead
    stage_w(smc, g_w2h, tid);
    __syncthreads();

    // ================= layer 2 (K=128, 8 kt) =================
#pragma unroll
    for (int nt = 0; nt < 4; nt++) wmma::fill_fragment(acc[nt], 0.f);

#pragma unroll 1
    for (int kt = 0; kt < 8; kt++) {
        wmma::load_matrix_sync(ah, AH + m0 * WSTR + kt * 16, WSTR);
        wmma::load_matrix_sync(al, AL + m0 * WSTR + kt * 16, WSTR);
#pragma unroll
        for (int nt = 0; nt < 4; nt++) {
            const int n = nh * 4 + nt;
            wmma::load_matrix_sync(bf, WB + n * 16 * WSTR + kt * 16, WSTR);
            wmma::mma_sync(acc[nt], ah, bf, acc[nt]);
            wmma::mma_sync(acc[nt], al, bf, acc[nt]);
        }
    }
    __syncthreads();
    stage_w(smc, g_w2l, tid);
    __syncthreads();

#pragma unroll 1
    for (int kt = 0; kt < 8; kt++) {
        wmma::load_matrix_sync(ah, AH + m0 * WSTR + kt * 16, WSTR);
#pragma unroll
        for (int nt = 0; nt < 4; nt++) {
            const int n = nh * 4 + nt;
            wmma::load_matrix_sync(bf, WB + n * 16 * WSTR + kt * 16, WSTR);
            wmma::mma_sync(acc[nt], ah, bf, acc[nt]);
        }
    }
    __syncthreads();   // W dead -> Cf reuse

    // ---- epilogue 2: acc -> Cf -> bias -> coalesced out ----
#pragma unroll
    for (int nt = 0; nt < 4; nt++)
        wmma::store_matrix_sync(Cf + m0 * CSTR + nh * 64 + nt * 16, acc[nt], CSTR,
                                wmma::mem_row_major);
    __syncthreads();
    {
        float* ob = out + (size_t)b * OUTC * NN + n0;
        for (int idx = tid; idx < 128 * 64; idx += 256) {
            const int c = idx >> 6;
            const int m = idx & 63;
            ob[(size_t)c * NN + m] = Cf[m * CSTR + c] + b2s[c];
        }
    }
}

// ---------------------------------------------------------------------------
extern "C" void kernel_launch(void* const* d_in, const int* in_sizes, int n_in,
                              void* d_out, int out_size) {
    const float* x   = (const float*)d_in[0];
    const float* sx  = (const float*)d_in[1];
    const float* ft  = (const float*)d_in[2];
    const float* w1  = (const float*)d_in[3];
    const float* b1  = (const float*)d_in[4];
    const float* w2  = (const float*)d_in[5];
    const float* b2  = (const float*)d_in[6];
    float* out = (float*)d_out;

    const int knn_smem = 2 * MH * sizeof(float4);   // 32 KB

    cudaFuncSetAttribute(knn_kernel,
                         cudaFuncAttributeMaxDynamicSharedMemorySize, knn_smem);
    cudaFuncSetAttribute(mlp_wmma_kernel,
                         cudaFuncAttributeMaxDynamicSharedMemorySize, MLP_SMEM);

    wprep_kernel<<<WP_BLOCKS, 128>>>(w1, w2);
    knn_kernel<<<(NQ / 256) * NSPLIT, 128, knn_smem>>>(x, sx);
    merge_kernel<<<NQ / 256, 256>>>();
    mlp_wmma_kernel<<<NQ / MTILE, 256, MLP_SMEM>>>(x, ft, b1, b2, out);
}

// round 16
// speedup vs baseline: 1.1088x; 1.0257x over previous
#include <cuda_runtime.h>
#include <cuda_bf16.h>
#include <math_constants.h>
#include <mma.h>

using namespace nvcuda;

#define BB 2
#define NN 32768
#define NQ (BB * NN)
#define MM 4096
#define MH 1024
#define NSPLIT 2
#define CC 128
#define OUTC 128
#define INC 131
#define MTILE 128

#define WSTR 144
#define CSTR 132

typedef unsigned long long ull;
typedef unsigned int uint;

// ---------------------------------------------------------------------------
__device__ __align__(16) __nv_bfloat16 g_w1h[128 * WSTR];
__device__ __align__(16) __nv_bfloat16 g_w1l[128 * WSTR];
__device__ __align__(16) __nv_bfloat16 g_w2h[128 * WSTR];
__device__ __align__(16) __nv_bfloat16 g_w2l[128 * WSTR];
__device__ int g_idx[NQ * 3];
__device__ float g_pv[NSPLIT * NQ * 3];
__device__ int   g_pi[NSPLIT * NQ * 3];

// ---------------------------------------------------------------------------
__device__ __forceinline__ ull fma2(ull a, ull b, ull c) {
    ull d;
    asm("fma.rn.f32x2 %0, %1, %2, %3;" : "=l"(d) : "l"(a), "l"(b), "l"(c));
    return d;
}
__device__ __forceinline__ ull pack2(float a, float b) {
    ull r;
    asm("mov.b64 %0, {%1, %2};" : "=l"(r)
        : "r"(__float_as_uint(a)), "r"(__float_as_uint(b)));
    return r;
}
__device__ __forceinline__ float2 unpack2(ull v) {
    unsigned int lo, hi;
    asm("mov.b64 {%0, %1}, %2;" : "=r"(lo), "=r"(hi) : "l"(v));
    return make_float2(__uint_as_float(lo), __uint_as_float(hi));
}
__device__ __forceinline__ void bmerge(float v, int j,
    float& m0, float& m1, float& m2, int& i0, int& i1, int& i2) {
    bool p0 = v < m0, p1 = v < m1, p2 = v < m2;
    float nm2 = p1 ? m1 : (p2 ? v : m2);
    int   ni2 = p1 ? i1 : (p2 ? j : i2);
    float nm1 = p0 ? m0 : (p1 ? v : m1);
    int   ni1 = p0 ? i0 : (p1 ? j : i1);
    float nm0 = p0 ? v : m0;
    int   ni0 = p0 ? j : i0;
    m0 = nm0; m1 = nm1; m2 = nm2;
    i0 = ni0; i1 = ni1; i2 = ni2;
}

// ---------------------------------------------------------------------------
// Kernel 0: weight prep
// ---------------------------------------------------------------------------
#define WP_ITEMS (2 * 128 * WSTR)
#define WP_BLOCKS ((WP_ITEMS + 127) / 128)

__global__ void __launch_bounds__(128) wprep_kernel(
    const float* __restrict__ w1, const float* __restrict__ w2) {
    int i = blockIdx.x * 128 + threadIdx.x;
    if (i >= WP_ITEMS) return;
    int which = i / (128 * WSTR);
    int t = i % (128 * WSTR);
    int row = t / WSTR, col = t % WSTR;
    float v = 0.f;
    if (which == 0) {
        if (col < 128)      v = w1[row * INC + 3 + col];
        else if (col < 131) v = w1[row * INC + (col - 128)];
    } else {
        if (col < 128)      v = w2[row * 128 + col];
    }
    __nv_bfloat16 hi = __float2bfloat16_rn(v);
    __nv_bfloat16 lo = __float2bfloat16_rn(v - __bfloat162float(hi));
    if (which == 0) { g_w1h[t] = hi; g_w1l[t] = lo; }
    else            { g_w2h[t] = hi; g_w2l[t] = lo; }
}

// ---------------------------------------------------------------------------
// Kernel 1: kNN, 2-way M-split (frozen from R15)
// ---------------------------------------------------------------------------
__global__ void __launch_bounds__(128) knn_kernel(
    const float* __restrict__ x, const float* __restrict__ sx) {
    extern __shared__ float4 sm4[];
    float4* skA = sm4;
    float4* skB = sm4 + MH;

    const int half = blockIdx.x & 1;
    const int q0   = (blockIdx.x >> 1) * 256;
    const int b    = q0 / NN;
    const int tid  = threadIdx.x;
    const int jbase = half * (2 * MH);

    const float* sxb = sx + (size_t)b * MM * 3 + (size_t)half * MH * 6;
    for (int j2 = tid; j2 < MH; j2 += 128) {
        const float* p = sxb + (size_t)j2 * 6;
        float a0 = p[0], a1 = p[1], a2 = p[2];
        float c0 = p[3], c1 = p[4], c2 = p[5];
        skA[j2] = make_float4(-2.f * a0, -2.f * c0, -2.f * a1, -2.f * c1);
        skB[j2] = make_float4(-2.f * a2, -2.f * c2,
                              a0 * a0 + a1 * a1 + a2 * a2,
                              c0 * c0 + c1 * c1 + c2 * c2);
    }
    __syncthreads();

    const int qa = q0 + tid;
    const int qb = q0 + 128 + tid;
    float xa0 = x[qa * 3 + 0], xa1 = x[qa * 3 + 1], xa2 = x[qa * 3 + 2];
    float xb0 = x[qb * 3 + 0], xb1 = x[qb * 3 + 1], xb2 = x[qb * 3 + 2];
    const ull ax0 = pack2(xa0, xa0), ax1 = pack2(xa1, xa1), ax2 = pack2(xa2, xa2);
    const ull bx0 = pack2(xb0, xb0), bx1 = pack2(xb1, xb1), bx2 = pack2(xb2, xb2);

    const ulonglong2* A2 = (const ulonglong2*)skA;
    const ulonglong2* B2 = (const ulonglong2*)skB;

    float am0 = CUDART_INF_F, am1 = CUDART_INF_F, am2 = CUDART_INF_F;
    float bm0 = CUDART_INF_F, bm1 = CUDART_INF_F, bm2 = CUDART_INF_F;
    unsigned fa[4], fb[4];

#pragma unroll
    for (int w4 = 0; w4 < 4; w4++) {
        unsigned fma_ = 0, fmb_ = 0;
#pragma unroll 1
        for (int cb = 0; cb < 32; cb++) {
            const int jc = w4 * 256 + cb * 8;
            float pa[8], pb_[8];
#pragma unroll
            for (int u = 0; u < 8; u++) {
                ulonglong2 A  = A2[jc + u];
                ulonglong2 Bv = B2[jc + u];
                ull da = fma2(Bv.x, ax2, Bv.y);
                da = fma2(A.y, ax1, da);
                da = fma2(A.x, ax0, da);
                float2 va = unpack2(da);
                pa[u] = fminf(va.x, va.y);
                ull db = fma2(Bv.x, bx2, Bv.y);
                db = fma2(A.y, bx1, db);
                db = fma2(A.x, bx0, db);
                float2 vb = unpack2(db);
                pb_[u] = fminf(vb.x, vb.y);
            }
            float ca = fminf(fminf(fminf(pa[0], pa[1]), fminf(pa[2], pa[3])),
                             fminf(fminf(pa[4], pa[5]), fminf(pa[6], pa[7])));
            float cbv = fminf(fminf(fminf(pb_[0], pb_[1]), fminf(pb_[2], pb_[3])),
                              fminf(fminf(pb_[4], pb_[5]), fminf(pb_[6], pb_[7])));
            fma_ |= (ca  <= am2) ? (1u << cb) : 0u;
            fmb_ |= (cbv <= bm2) ? (1u << cb) : 0u;
            am2 = fminf(am2, fmaxf(am1, ca));
            am1 = fminf(am1, fmaxf(am0, ca));
            am0 = fminf(am0, ca);
            bm2 = fminf(bm2, fmaxf(bm1, cbv));
            bm1 = fminf(bm1, fmaxf(bm0, cbv));
            bm0 = fminf(bm0, cbv);
        }
        fa[w4] = fma_;
        fb[w4] = fmb_;
    }

    const size_t pbase = (size_t)half * NQ * 3;
    {
        float n0 = CUDART_INF_F, n1 = CUDART_INF_F, n2 = CUDART_INF_F;
        int   i0 = 0, i1 = 0, i2 = 0;
#pragma unroll
        for (int w4 = 0; w4 < 4; w4++) {
            unsigned fm = fa[w4];
            while (fm) {
                const int cb = __ffs(fm) - 1;
                fm &= fm - 1;
                const int jc = w4 * 256 + cb * 8;
#pragma unroll
                for (int u = 0; u < 8; u++) {
                    ulonglong2 A  = A2[jc + u];
                    ulonglong2 Bv = B2[jc + u];
                    ull d = fma2(Bv.x, ax2, Bv.y);
                    d = fma2(A.y, ax1, d);
                    d = fma2(A.x, ax0, d);
                    float2 vv = unpack2(d);
                    bmerge(vv.x, jbase + 2 * (jc + u),     n0, n1, n2, i0, i1, i2);
                    bmerge(vv.y, jbase + 2 * (jc + u) + 1, n0, n1, n2, i0, i1, i2);
                }
            }
        }
        g_pv[pbase + qa * 3 + 0] = n0; g_pi[pbase + qa * 3 + 0] = i0;
        g_pv[pbase + qa * 3 + 1] = n1; g_pi[pbase + qa * 3 + 1] = i1;
        g_pv[pbase + qa * 3 + 2] = n2; g_pi[pbase + qa * 3 + 2] = i2;
    }
    {
        float n0 = CUDART_INF_F, n1 = CUDART_INF_F, n2 = CUDART_INF_F;
        int   i0 = 0, i1 = 0, i2 = 0;
#pragma unroll
        for (int w4 = 0; w4 < 4; w4++) {
            unsigned fm = fb[w4];
            while (fm) {
                const int cb = __ffs(fm) - 1;
                fm &= fm - 1;
                const int jc = w4 * 256 + cb * 8;
#pragma unroll
                for (int u = 0; u < 8; u++) {
                    ulonglong2 A  = A2[jc + u];
                    ulonglong2 Bv = B2[jc + u];
                    ull d = fma2(Bv.x, bx2, Bv.y);
                    d = fma2(A.y, bx1, d);
                    d = fma2(A.x, bx0, d);
                    float2 vv = unpack2(d);
                    bmerge(vv.x, jbase + 2 * (jc + u),     n0, n1, n2, i0, i1, i2);
                    bmerge(vv.y, jbase + 2 * (jc + u) + 1, n0, n1, n2, i0, i1, i2);
                }
            }
        }
        g_pv[pbase + qb * 3 + 0] = n0; g_pi[pbase + qb * 3 + 0] = i0;
        g_pv[pbase + qb * 3 + 1] = n1; g_pi[pbase + qb * 3 + 1] = i1;
        g_pv[pbase + qb * 3 + 2] = n2; g_pi[pbase + qb * 3 + 2] = i2;
    }
}

// ---------------------------------------------------------------------------
__global__ void __launch_bounds__(256) merge_kernel() {
    int q = blockIdx.x * 256 + threadIdx.x;
    if (q >= NQ) return;
    float m0 = g_pv[q * 3 + 0], m1 = g_pv[q * 3 + 1], m2 = g_pv[q * 3 + 2];
    int   i0 = g_pi[q * 3 + 0], i1 = g_pi[q * 3 + 1], i2 = g_pi[q * 3 + 2];
    const size_t o = (size_t)NQ * 3;
#pragma unroll
    for (int k = 0; k < 3; k++)
        bmerge(g_pv[o + q * 3 + k], g_pi[o + q * 3 + k], m0, m1, m2, i0, i1, i2);
    g_idx[q * 3 + 0] = i0;
    g_idx[q * 3 + 1] = i1;
    g_idx[q * 3 + 2] = i2;
}

// ---------------------------------------------------------------------------
// Kernel 2: WMMA bf16-split MLP, 128-pt tile, 32-row m-strips, W-phase split.
//   8 warps = 4 m-strips(32 rows) x 2 n-halves(64 cols); acc[2][4]/warp.
//   SMEM: AH(36.9K) | AL(36.9K) | W(36.9K, restaged 4x) | bias -> 109KB, 2 blk/SM
//   Epilogues in two 64-row rounds (Cf 33.8KB aliases dead W region).
// ---------------------------------------------------------------------------
#define SM_AH   0
#define SM_AL   (SM_AH + MTILE * WSTR * 2)   // 36864
#define SM_W    (SM_AL + MTILE * WSTR * 2)   // 73728
#define SM_BIAS (SM_W + 128 * WSTR * 2)      // 110592
#define MLP_SMEM (SM_BIAS + 1024)            // 111616

__device__ __forceinline__ void stage_w(char* smc, const __nv_bfloat16* src, int tid) {
    const uint4* s = (const uint4*)src;
#pragma unroll
    for (int r = 0; r < 9; r++) {
        int i = tid + r * 256;
        *(uint4*)(smc + SM_W + i * 16) = s[i];
    }
}

__global__ void __launch_bounds__(256, 2) mlp_wmma_kernel(
    const float* __restrict__ x, const float* __restrict__ feat,
    const float* __restrict__ b1, const float* __restrict__ b2,
    float* __restrict__ out) {
    extern __shared__ char smc[];
    __nv_bfloat16* AH = (__nv_bfloat16*)(smc + SM_AH);
    __nv_bfloat16* AL = (__nv_bfloat16*)(smc + SM_AL);
    __nv_bfloat16* WB = (__nv_bfloat16*)(smc + SM_W);
    float*         Cf = (float*)(smc + SM_W);      // 64*132*4 = 33792 <= 36864
    float*         b1s = (float*)(smc + SM_BIAS);
    float*         b2s = b1s + 128;

    const int tid  = threadIdx.x;
    const int wid  = tid >> 5;
    const int lane = tid & 31;
    const int ms   = wid & 3;       // m-strip of 32 rows
    const int nh   = wid >> 2;      // n-half (64 cols)
    const int p0   = blockIdx.x * MTILE;
    const int b    = p0 / NN;
    const int n0   = p0 - b * NN;
    const int m0   = ms * 32;

    // ---- zero A + stage biases + stage W1h ----
    {
        uint4 z = make_uint4(0, 0, 0, 0);
        for (int i = tid; i < MTILE * WSTR * 4 / 16; i += 256)
            *(uint4*)(smc + SM_AH + i * 16) = z;
        if (tid < 128) { b1s[tid] = b1[tid]; b2s[tid] = b2[tid]; }
        stage_w(smc, g_w1h, tid);
    }
    __syncthreads();

    // ---- gather + bf16 split into AH/AL (8 warps x 16 points) ----
    {
        const float4* F = (const float4*)feat;
#pragma unroll 1
        for (int t = 0; t < 16; t++) {
            const int pt = wid * 16 + t;
            const int gq = p0 + pt;
            const int j0 = g_idx[gq * 3 + 0];
            const int j1 = g_idx[gq * 3 + 1];
            const int j2 = g_idx[gq * 3 + 2];
            float4 f0 = F[(size_t)(b * MM + j0) * 32 + lane];
            float4 f1 = F[(size_t)(b * MM + j1) * 32 + lane];
            float4 f2 = F[(size_t)(b * MM + j2) * 32 + lane];
            float v[4];
            v[0] = (f0.x + f1.x + f2.x) * (1.f / 3.f);
            v[1] = (f0.y + f1.y + f2.y) * (1.f / 3.f);
            v[2] = (f0.z + f1.z + f2.z) * (1.f / 3.f);
            v[3] = (f0.w + f1.w + f2.w) * (1.f / 3.f);
            uint hw[2], lw[2];
#pragma unroll
            for (int q = 0; q < 2; q++) {
                __nv_bfloat16 h0 = __float2bfloat16_rn(v[2 * q]);
                __nv_bfloat16 h1 = __float2bfloat16_rn(v[2 * q + 1]);
                __nv_bfloat16 l0 = __float2bfloat16_rn(v[2 * q] - __bfloat162float(h0));
                __nv_bfloat16 l1 = __float2bfloat16_rn(v[2 * q + 1] - __bfloat162float(h1));
                hw[q] = (uint)__bfloat16_as_ushort(h0) | ((uint)__bfloat16_as_ushort(h1) << 16);
                lw[q] = (uint)__bfloat16_as_ushort(l0) | ((uint)__bfloat16_as_ushort(l1) << 16);
            }
            *(uint2*)&AH[pt * WSTR + 4 * lane] = make_uint2(hw[0], hw[1]);
            *(uint2*)&AL[pt * WSTR + 4 * lane] = make_uint2(lw[0], lw[1]);
            if (lane == 0) {
                float c0 = x[gq * 3 + 0], c1 = x[gq * 3 + 1], c2 = x[gq * 3 + 2];
                __nv_bfloat16 h0 = __float2bfloat16_rn(c0);
                __nv_bfloat16 h1 = __float2bfloat16_rn(c1);
                __nv_bfloat16 h2 = __float2bfloat16_rn(c2);
                __nv_bfloat16 l0 = __float2bfloat16_rn(c0 - __bfloat162float(h0));
                __nv_bfloat16 l1 = __float2bfloat16_rn(c1 - __bfloat162float(h1));
                __nv_bfloat16 l2 = __float2bfloat16_rn(c2 - __bfloat162float(h2));
                *(uint2*)&AH[pt * WSTR + 128] = make_uint2(
                    (uint)__bfloat16_as_ushort(h0) | ((uint)__bfloat16_as_ushort(h1) << 16),
                    (uint)__bfloat16_as_ushort(h2));
                *(uint2*)&AL[pt * WSTR + 128] = make_uint2(
                    (uint)__bfloat16_as_ushort(l0) | ((uint)__bfloat16_as_ushort(l1) << 16),
                    (uint)__bfloat16_as_ushort(l2));
            }
        }
    }
    __syncthreads();

    wmma::fragment<wmma::accumulator, 16, 16, 16, float> acc0[4], acc1[4];
    wmma::fragment<wmma::matrix_a, 16, 16, 16, __nv_bfloat16, wmma::row_major> ah0, al0, ah1, al1;
    wmma::fragment<wmma::matrix_b, 16, 16, 16, __nv_bfloat16, wmma::col_major> bf;

    // ================= layer 1 (K=144, 9 kt) =================
#pragma unroll
    for (int nt = 0; nt < 4; nt++) {
        wmma::fill_fragment(acc0[nt], 0.f);
        wmma::fill_fragment(acc1[nt], 0.f);
    }

    // phase A: W = W1h -> acc += Ah*Bh + Al*Bh
#pragma unroll 1
    for (int kt = 0; kt < 9; kt++) {
        wmma::load_matrix_sync(ah0, AH + m0 * WSTR + kt * 16, WSTR);
        wmma::load_matrix_sync(al0, AL + m0 * WSTR + kt * 16, WSTR);
        wmma::load_matrix_sync(ah1, AH + (m0 + 16) * WSTR + kt * 16, WSTR);
        wmma::load_matrix_sync(al1, AL + (m0 + 16) * WSTR + kt * 16, WSTR);
#pragma unroll
        for (int nt = 0; nt < 4; nt++) {
            const int n = nh * 4 + nt;
            wmma::load_matrix_sync(bf, WB + n * 16 * WSTR + kt * 16, WSTR);
            wmma::mma_sync(acc0[nt], ah0, bf, acc0[nt]);
            wmma::mma_sync(acc0[nt], al0, bf, acc0[nt]);
            wmma::mma_sync(acc1[nt], ah1, bf, acc1[nt]);
            wmma::mma_sync(acc1[nt], al1, bf, acc1[nt]);
        }
    }
    __syncthreads();
    stage_w(smc, g_w1l, tid);
    __syncthreads();

    // phase B: W = W1l -> acc += Ah*Bl
#pragma unroll 1
    for (int kt = 0; kt < 9; kt++) {
        wmma::load_matrix_sync(ah0, AH + m0 * WSTR + kt * 16, WSTR);
        wmma::load_matrix_sync(ah1, AH + (m0 + 16) * WSTR + kt * 16, WSTR);
#pragma unroll
        for (int nt = 0; nt < 4; nt++) {
            const int n = nh * 4 + nt;
            wmma::load_matrix_sync(bf, WB + n * 16 * WSTR + kt * 16, WSTR);
            wmma::mma_sync(acc0[nt], ah0, bf, acc0[nt]);
            wmma::mma_sync(acc1[nt], ah1, bf, acc1[nt]);
        }
    }
    __syncthreads();   // W dead -> Cf may overwrite

    // ---- epilogue 1 (two 64-row rounds): bias+relu -> split -> AH/AL ----
#pragma unroll 1
    for (int r = 0; r < 2; r++) {
        if ((ms >> 1) == r) {
            const int mr = m0 - r * 64;
#pragma unroll
            for (int nt = 0; nt < 4; nt++) {
                wmma::store_matrix_sync(Cf + mr * CSTR + nh * 64 + nt * 16,
                                        acc0[nt], CSTR, wmma::mem_row_major);
                wmma::store_matrix_sync(Cf + (mr + 16) * CSTR + nh * 64 + nt * 16,
                                        acc1[nt], CSTR, wmma::mem_row_major);
            }
        }
        __syncthreads();
#pragma unroll 1
        for (int idx = tid; idx < 64 * 64; idx += 256) {
            const int m = idx >> 6;
            const int c = (idx & 63) * 2;
            float v0 = fmaxf(Cf[m * CSTR + c]     + b1s[c],     0.f);
            float v1 = fmaxf(Cf[m * CSTR + c + 1] + b1s[c + 1], 0.f);
            __nv_bfloat16 h0 = __float2bfloat16_rn(v0);
            __nv_bfloat16 h1 = __float2bfloat16_rn(v1);
            __nv_bfloat16 l0 = __float2bfloat16_rn(v0 - __bfloat162float(h0));
            __nv_bfloat16 l1 = __float2bfloat16_rn(v1 - __bfloat162float(h1));
            const int mg = r * 64 + m;
            *(uint*)&AH[mg * WSTR + c] =
                (uint)__bfloat16_as_ushort(h0) | ((uint)__bfloat16_as_ushort(h1) << 16);
            *(uint*)&AL[mg * WSTR + c] =
                (uint)__bfloat16_as_ushort(l0) | ((uint)__bfloat16_as_ushort(l1) << 16);
        }
        __syncthreads();
    }
    stage_w(smc, g_w2h, tid);
    __syncthreads();

    // ================= layer 2 (K=128, 8 kt) =================
#pragma unroll
    for (int nt = 0; nt < 4; nt++) {
        wmma::fill_fragment(acc0[nt], 0.f);
        wmma::fill_fragment(acc1[nt], 0.f);
    }

#pragma unroll 1
    for (int kt = 0; kt < 8; kt++) {
        wmma::load_matrix_sync(ah0, AH + m0 * WSTR + kt * 16, WSTR);
        wmma::load_matrix_sync(al0, AL + m0 * WSTR + kt * 16, WSTR);
        wmma::load_matrix_sync(ah1, AH + (m0 + 16) * WSTR + kt * 16, WSTR);
        wmma::load_matrix_sync(al1, AL + (m0 + 16) * WSTR + kt * 16, WSTR);
#pragma unroll
        for (int nt = 0; nt < 4; nt++) {
            const int n = nh * 4 + nt;
            wmma::load_matrix_sync(bf, WB + n * 16 * WSTR + kt * 16, WSTR);
            wmma::mma_sync(acc0[nt], ah0, bf, acc0[nt]);
            wmma::mma_sync(acc0[nt], al0, bf, acc0[nt]);
            wmma::mma_sync(acc1[nt], ah1, bf, acc1[nt]);
            wmma::mma_sync(acc1[nt], al1, bf, acc1[nt]);
        }
    }
    __syncthreads();
    stage_w(smc, g_w2l, tid);
    __syncthreads();

#pragma unroll 1
    for (int kt = 0; kt < 8; kt++) {
        wmma::load_matrix_sync(ah0, AH + m0 * WSTR + kt * 16, WSTR);
        wmma::load_matrix_sync(ah1, AH + (m0 + 16) * WSTR + kt * 16, WSTR);
#pragma unroll
        for (int nt = 0; nt < 4; nt++) {
            const int n = nh * 4 + nt;
            wmma::load_matrix_sync(bf, WB + n * 16 * WSTR + kt * 16, WSTR);
            wmma::mma_sync(acc0[nt], ah0, bf, acc0[nt]);
            wmma::mma_sync(acc1[nt], ah1, bf, acc1[nt]);
        }
    }
    __syncthreads();   // W dead -> Cf reuse

    // ---- epilogue 2 (two 64-row rounds): bias -> coalesced out ----
#pragma unroll 1
    for (int r = 0; r < 2; r++) {
        if ((ms >> 1) == r) {
            const int mr = m0 - r * 64;
#pragma unroll
            for (int nt = 0; nt < 4; nt++) {
                wmma::store_matrix_sync(Cf + mr * CSTR + nh * 64 + nt * 16,
                                        acc0[nt], CSTR, wmma::mem_row_major);
                wmma::store_matrix_sync(Cf + (mr + 16) * CSTR + nh * 64 + nt * 16,
                                        acc1[nt], CSTR, wmma::mem_row_major);
            }
        }
        __syncthreads();
        {
            float* ob = out + (size_t)b * OUTC * NN + n0 + r * 64;
            for (int idx = tid; idx < 128 * 64; idx += 256) {
                const int c = idx >> 6;
                const int m = idx & 63;
                ob[(size_t)c * NN + m] = Cf[m * CSTR + c] + b2s[c];
            }
        }
        __syncthreads();
    }
}

// ---------------------------------------------------------------------------
extern "C" void kernel_launch(void* const* d_in, const int* in_sizes, int n_in,
                              void* d_out, int out_size) {
    const float* x   = (const float*)d_in[0];
    const float* sx  = (const float*)d_in[1];
    const float* ft  = (const float*)d_in[2];
    const float* w1  = (const float*)d_in[3];
    const float* b1  = (const float*)d_in[4];
    const float* w2  = (const float*)d_in[5];
    const float* b2  = (const float*)d_in[6];
    float* out = (float*)d_out;

    const int knn_smem = 2 * MH * sizeof(float4);   // 32 KB

    cudaFuncSetAttribute(knn_kernel,
                         cudaFuncAttributeMaxDynamicSharedMemorySize, knn_smem);
    cudaFuncSetAttribute(mlp_wmma_kernel,
                         cudaFuncAttributeMaxDynamicSharedMemorySize, MLP_SMEM);

    wprep_kernel<<<WP_BLOCKS, 128>>>(w1, w2);
    knn_kernel<<<(NQ / 256) * NSPLIT, 128, knn_smem>>>(x, sx);
    merge_kernel<<<NQ / 256, 256>>>();
    mlp_wmma_kernel<<<NQ / MTILE, 256, MLP_SMEM>>>(x, ft, b1, b2, out);
}